// round 1
// baseline (speedup 1.0000x reference)
#include <cuda_runtime.h>
#include <math.h>

#define N_NODES 100000
#define N_EDGES 1600000
#define D 128
#define H 128
#define EC 16
#define KF (2*H + EC)   // 272

// ---------------- scratch (device globals: allocation-free) ----------------
__device__ float g_msg[N_NODES * H];   // 51.2 MB
__device__ float g_deg[N_NODES];
__device__ float g_h0[N_NODES * H];
__device__ float g_h1[N_NODES * H];

// ---------------- zero scratch ----------------
__global__ void zero_kernel(int zero_deg) {
    int idx = blockIdx.x * blockDim.x + threadIdx.x;
    int stride = gridDim.x * blockDim.x;
    int n4 = N_NODES * H / 4;
    float4 z = make_float4(0.f, 0.f, 0.f, 0.f);
    for (int i = idx; i < n4; i += stride)
        ((float4*)g_msg)[i] = z;
    if (zero_deg) {
        for (int i = idx; i < N_NODES; i += stride)
            g_deg[i] = 0.f;
    }
}

// ---------------- scatter: msg[dst] += feat[src], deg[dst] += 1 ----------------
__global__ void scatter_kernel(const float* __restrict__ feat,
                               const int* __restrict__ src,
                               const int* __restrict__ dst,
                               int count_deg) {
    int idx = blockIdx.x * blockDim.x + threadIdx.x;
    if (idx >= N_EDGES * 32) return;
    int e = idx >> 5;
    int c = idx & 31;
    int s = __ldg(src + e);
    int d = __ldg(dst + e);
    float4 v = *(const float4*)(feat + (size_t)s * H + c * 4);
    float* p = g_msg + (size_t)d * H + c * 4;
    asm volatile("red.global.add.v4.f32 [%0], {%1, %2, %3, %4};"
                 :: "l"(p), "f"(v.x), "f"(v.y), "f"(v.z), "f"(v.w) : "memory");
    if (count_deg && c == 0) atomicAdd(g_deg + d, 1.0f);
}

// ---------------- SAGE layer: out = relu((msg/deg)@Wl + b + xin@Wr) ----------------
// 512 threads, 64-row tiles, both 128x128 weights in smem, 4x4 register micro-tile.
#define SAGE_ROWS 64
#define SAGE_SMEM_FLOATS (16384 + 16384 + 8192 + 8192 + 64)

__global__ void __launch_bounds__(512, 1) sage_kernel(
    const float* __restrict__ xin, const float* __restrict__ Wl,
    const float* __restrict__ Wr, const float* __restrict__ b,
    float* __restrict__ out)
{
    extern __shared__ float sm[];
    float* WlS = sm;                 // 128*128
    float* WrS = sm + 16384;         // 128*128
    float* aS  = sm + 32768;         // 64*128
    float* xS  = sm + 40960;         // 64*128
    float* idS = sm + 49152;         // 64

    int tid = threadIdx.x;

    for (int i = tid; i < 16384 / 4; i += 512) {
        ((float4*)WlS)[i] = ((const float4*)Wl)[i];
        ((float4*)WrS)[i] = ((const float4*)Wr)[i];
    }

    int ntiles = (N_NODES + SAGE_ROWS - 1) / SAGE_ROWS;
    int cg = tid & 31;        // column group: cols cg*4 .. cg*4+3
    int rg = tid >> 5;        // row group: rows rg*4 .. rg*4+3  (16 groups * 4 = 64)

    for (int t = blockIdx.x; t < ntiles; t += gridDim.x) {
        int r0 = t * SAGE_ROWS;
        if (tid < SAGE_ROWS) {
            int node = r0 + tid;
            float dg = (node < N_NODES) ? g_deg[node] : 1.f;
            idS[tid] = 1.f / fmaxf(dg, 1.f);
        }
        __syncthreads();
        for (int i = tid; i < SAGE_ROWS * 32; i += 512) {   // float4 units
            int row = i >> 5;
            int c4  = i & 31;
            int node = r0 + row;
            float4 m, xv;
            if (node < N_NODES) {
                m  = ((const float4*)(g_msg + (size_t)node * H))[c4];
                float inv = idS[row];
                m.x *= inv; m.y *= inv; m.z *= inv; m.w *= inv;
                xv = ((const float4*)(xin + (size_t)node * H))[c4];
            } else {
                m = make_float4(0.f,0.f,0.f,0.f); xv = m;
            }
            ((float4*)aS)[i] = m;
            ((float4*)xS)[i] = xv;
        }
        __syncthreads();

        float acc[4][4];
        #pragma unroll
        for (int i = 0; i < 4; i++)
            #pragma unroll
            for (int j = 0; j < 4; j++) acc[i][j] = 0.f;

        #pragma unroll 4
        for (int k = 0; k < D; k++) {
            float4 wl = *(const float4*)(WlS + k * 128 + cg * 4);
            float4 wr = *(const float4*)(WrS + k * 128 + cg * 4);
            #pragma unroll
            for (int i = 0; i < 4; i++) {
                float a  = aS[(rg * 4 + i) * 128 + k];
                float xx = xS[(rg * 4 + i) * 128 + k];
                acc[i][0] = fmaf(a, wl.x, acc[i][0]);
                acc[i][1] = fmaf(a, wl.y, acc[i][1]);
                acc[i][2] = fmaf(a, wl.z, acc[i][2]);
                acc[i][3] = fmaf(a, wl.w, acc[i][3]);
                acc[i][0] = fmaf(xx, wr.x, acc[i][0]);
                acc[i][1] = fmaf(xx, wr.y, acc[i][1]);
                acc[i][2] = fmaf(xx, wr.z, acc[i][2]);
                acc[i][3] = fmaf(xx, wr.w, acc[i][3]);
            }
        }

        float4 bb = *(const float4*)(b + cg * 4);
        #pragma unroll
        for (int i = 0; i < 4; i++) {
            int node = r0 + rg * 4 + i;
            if (node < N_NODES) {
                float4 o;
                o.x = fmaxf(acc[i][0] + bb.x, 0.f);
                o.y = fmaxf(acc[i][1] + bb.y, 0.f);
                o.z = fmaxf(acc[i][2] + bb.z, 0.f);
                o.w = fmaxf(acc[i][3] + bb.w, 0.f);
                *(float4*)(out + (size_t)node * H + cg * 4) = o;
            }
        }
        __syncthreads();
    }
}

// ---------------- edge classifier: feat=[h[src],h[dst],eattr] -> 128 -> 64 -> 1 -> sigmoid ----
// 512 threads, 32-edge tiles. Wc1 (272x128) + Wc2 (128x64) resident in smem.
#define ETILE 32
#define CLS_SMEM_FLOATS (34816 + 8192 + ETILE*KF + ETILE*129 + ETILE*64)

__global__ void __launch_bounds__(512, 1) cls_kernel(
    const float* __restrict__ h, const int* __restrict__ src,
    const int* __restrict__ dst, const float* __restrict__ eattr,
    const float* __restrict__ Wc1, const float* __restrict__ bc1,
    const float* __restrict__ Wc2, const float* __restrict__ bc2,
    const float* __restrict__ Wc3, const float* __restrict__ bc3,
    float* __restrict__ out)
{
    extern __shared__ float sm[];
    float* W1S   = sm;                          // 272*128 = 34816
    float* W2S   = W1S + 34816;                 // 128*64  = 8192
    float* featS = W2S + 8192;                  // 32*272  = 8704
    float* z1S   = featS + ETILE * KF;          // 32*129  = 4128 (padded stride)
    float* z2S   = z1S + ETILE * 129;           // 32*64   = 2048

    int tid = threadIdx.x;

    for (int i = tid; i < 34816 / 4; i += 512)
        ((float4*)W1S)[i] = ((const float4*)Wc1)[i];
    for (int i = tid; i < 8192 / 4; i += 512)
        ((float4*)W2S)[i] = ((const float4*)Wc2)[i];

    int ntiles = (N_EDGES + ETILE - 1) / ETILE;

    for (int t = blockIdx.x; t < ntiles; t += gridDim.x) {
        int e0 = t * ETILE;
        __syncthreads();   // guards weight load (1st iter) and smem reuse across tiles

        // Stage A: build feature tile [32][272]
        for (int i = tid; i < ETILE * KF; i += 512) {
            int el = i / KF;
            int c  = i - el * KF;
            int e  = e0 + el;
            float v = 0.f;
            if (e < N_EDGES) {
                if (c < H)            v = h[(size_t)__ldg(src + e) * H + c];
                else if (c < 2 * H)   v = h[(size_t)__ldg(dst + e) * H + (c - H)];
                else                  v = eattr[(size_t)e * EC + (c - 2 * H)];
            }
            featS[el * KF + c] = v;
        }
        __syncthreads();

        // Stage B: z1 = relu(feat @ Wc1 + bc1)  — thread = 2 edges x 4 cols
        {
            int cg = tid & 31;      // cols cg*4..+3
            int eg = tid >> 5;      // edges eg*2, eg*2+1
            float4 b1 = *(const float4*)(bc1 + cg * 4);
            float a00 = b1.x, a01 = b1.y, a02 = b1.z, a03 = b1.w;
            float a10 = b1.x, a11 = b1.y, a12 = b1.z, a13 = b1.w;
            const float* f0 = featS + (eg * 2) * KF;
            const float* f1 = f0 + KF;
            #pragma unroll 4
            for (int k = 0; k < KF; k++) {
                float4 w = *(const float4*)(W1S + k * 128 + cg * 4);
                float a0 = f0[k];
                float a1 = f1[k];
                a00 = fmaf(a0, w.x, a00); a01 = fmaf(a0, w.y, a01);
                a02 = fmaf(a0, w.z, a02); a03 = fmaf(a0, w.w, a03);
                a10 = fmaf(a1, w.x, a10); a11 = fmaf(a1, w.y, a11);
                a12 = fmaf(a1, w.z, a12); a13 = fmaf(a1, w.w, a13);
            }
            float* z0 = z1S + (eg * 2) * 129 + cg * 4;
            float* z1 = z0 + 129;
            z0[0] = fmaxf(a00, 0.f); z0[1] = fmaxf(a01, 0.f);
            z0[2] = fmaxf(a02, 0.f); z0[3] = fmaxf(a03, 0.f);
            z1[0] = fmaxf(a10, 0.f); z1[1] = fmaxf(a11, 0.f);
            z1[2] = fmaxf(a12, 0.f); z1[3] = fmaxf(a13, 0.f);
        }
        __syncthreads();

        // Stage C: z2 = relu(z1 @ Wc2 + bc2)  — thread = 1 edge x 4 cols
        {
            int cg = tid & 15;      // cols cg*4..+3
            int e  = tid >> 4;      // 32 edges
            float4 b2 = *(const float4*)(bc2 + cg * 4);
            float c0 = b2.x, c1 = b2.y, c2 = b2.z, c3 = b2.w;
            const float* zp = z1S + e * 129;
            #pragma unroll 4
            for (int k = 0; k < H; k++) {
                float4 w = *(const float4*)(W2S + k * 64 + cg * 4);
                float a = zp[k];
                c0 = fmaf(a, w.x, c0); c1 = fmaf(a, w.y, c1);
                c2 = fmaf(a, w.z, c2); c3 = fmaf(a, w.w, c3);
            }
            float* z2p = z2S + e * 64 + cg * 4;
            z2p[0] = fmaxf(c0, 0.f); z2p[1] = fmaxf(c1, 0.f);
            z2p[2] = fmaxf(c2, 0.f); z2p[3] = fmaxf(c3, 0.f);
        }
        __syncthreads();

        // Stage D: logit + sigmoid — warp per 2 edges
        {
            int warp = tid >> 5, lane = tid & 31;
            float w3a = __ldg(Wc3 + lane);
            float w3b = __ldg(Wc3 + lane + 32);
            float b3  = __ldg(bc3);
            #pragma unroll
            for (int s = 0; s < 2; s++) {
                int el = warp * 2 + s;
                float p = z2S[el * 64 + lane] * w3a
                        + z2S[el * 64 + lane + 32] * w3b;
                #pragma unroll
                for (int o = 16; o > 0; o >>= 1)
                    p += __shfl_xor_sync(0xffffffffu, p, o);
                int e = e0 + el;
                if (lane == 0 && e < N_EDGES)
                    out[e] = 1.f / (1.f + expf(-(p + b3)));
            }
        }
    }
}

// ---------------- launch ----------------
extern "C" void kernel_launch(void* const* d_in, const int* in_sizes, int n_in,
                              void* d_out, int out_size) {
    const float* x     = (const float*)d_in[0];
    const int*   ei    = (const int*)d_in[1];
    const float* eattr = (const float*)d_in[2];
    const float* Wl0   = (const float*)d_in[3];
    const float* Wr0   = (const float*)d_in[4];
    const float* b0    = (const float*)d_in[5];
    const float* Wl1   = (const float*)d_in[6];
    const float* Wr1   = (const float*)d_in[7];
    const float* b1    = (const float*)d_in[8];
    const float* Wc1   = (const float*)d_in[9];
    const float* bc1   = (const float*)d_in[10];
    const float* Wc2   = (const float*)d_in[11];
    const float* bc2   = (const float*)d_in[12];
    const float* Wc3   = (const float*)d_in[13];
    const float* bc3   = (const float*)d_in[14];
    const int* src = ei;
    const int* dst = ei + N_EDGES;
    float* out = (float*)d_out;

    int sm_count = 148;
    cudaDeviceGetAttribute(&sm_count, cudaDevAttrMultiProcessorCount, 0);

    size_t sage_smem = SAGE_SMEM_FLOATS * sizeof(float);   // 196,864 B
    size_t cls_smem  = CLS_SMEM_FLOATS * sizeof(float);    // 231,552 B
    cudaFuncSetAttribute(sage_kernel, cudaFuncAttributeMaxDynamicSharedMemorySize,
                         (int)sage_smem);
    cudaFuncSetAttribute(cls_kernel, cudaFuncAttributeMaxDynamicSharedMemorySize,
                         (int)cls_smem);

    int scatter_blocks = (N_EDGES * 32) / 256;   // 200000

    // layer 0
    zero_kernel<<<4096, 256>>>(1);
    scatter_kernel<<<scatter_blocks, 256>>>(x, src, dst, 1);
    sage_kernel<<<sm_count, 512, sage_smem>>>(x, Wl0, Wr0, b0, g_h0);

    // layer 1 (deg unchanged, reuse)
    zero_kernel<<<4096, 256>>>(0);
    scatter_kernel<<<scatter_blocks, 256>>>(g_h0, src, dst, 0);
    sage_kernel<<<sm_count, 512, sage_smem>>>(g_h0, Wl1, Wr1, b1, g_h1);

    // classifier
    cls_kernel<<<sm_count, 512, cls_smem>>>(g_h1, src, dst, eattr,
                                            Wc1, bc1, Wc2, bc2, Wc3, bc3, out);
}

// round 4
// speedup vs baseline: 1.3762x; 1.3762x over previous
#include <cuda_runtime.h>
#include <cstdint>
#include <math.h>

#define N_NODES 100000
#define N_EDGES 1600000
#define D 128
#define H 128
#define EC 16

// ---------------- scratch (device globals: allocation-free) ----------------
__device__ float g_msg[N_NODES * H];   // 51.2 MB
__device__ float g_deg[N_NODES];
__device__ float g_h0[N_NODES * H];
__device__ float g_h1[N_NODES * H];

// ---------------- zero scratch ----------------
__global__ void zero_kernel(int zero_deg) {
    int idx = blockIdx.x * blockDim.x + threadIdx.x;
    int stride = gridDim.x * blockDim.x;
    int n4 = N_NODES * H / 4;
    float4 z = make_float4(0.f, 0.f, 0.f, 0.f);
    for (int i = idx; i < n4; i += stride)
        ((float4*)g_msg)[i] = z;
    if (zero_deg)
        for (int i = idx; i < N_NODES; i += stride)
            g_deg[i] = 0.f;
}

// ---------------- scatter: msg[dst] += feat[src], deg[dst] += 1 ----------------
__global__ void scatter_kernel(const float* __restrict__ feat,
                               const int* __restrict__ src,
                               const int* __restrict__ dst,
                               int count_deg) {
    int idx = blockIdx.x * blockDim.x + threadIdx.x;
    if (idx >= N_EDGES * 32) return;
    int e = idx >> 5;
    int c = idx & 31;
    int s = __ldg(src + e);
    int d = __ldg(dst + e);
    float4 v = *(const float4*)(feat + (size_t)s * H + c * 4);
    float* p = g_msg + (size_t)d * H + c * 4;
    asm volatile("red.global.add.v4.f32 [%0], {%1, %2, %3, %4};"
                 :: "l"(p), "f"(v.x), "f"(v.y), "f"(v.z), "f"(v.w) : "memory");
    if (count_deg && c == 0) atomicAdd(g_deg + d, 1.0f);
}

// ---------------- SAGE layer (fp32 SIMT) ----------------
#define SAGE_ROWS 64
#define SAGE_SMEM_FLOATS (16384 + 16384 + 8192 + 8192 + 64)

__global__ void __launch_bounds__(512, 1) sage_kernel(
    const float* __restrict__ xin, const float* __restrict__ Wl,
    const float* __restrict__ Wr, const float* __restrict__ b,
    float* __restrict__ out)
{
    extern __shared__ float sm[];
    float* WlS = sm;
    float* WrS = sm + 16384;
    float* aS  = sm + 32768;
    float* xS  = sm + 40960;
    float* idS = sm + 49152;

    int tid = threadIdx.x;
    for (int i = tid; i < 16384 / 4; i += 512) {
        ((float4*)WlS)[i] = ((const float4*)Wl)[i];
        ((float4*)WrS)[i] = ((const float4*)Wr)[i];
    }
    int ntiles = (N_NODES + SAGE_ROWS - 1) / SAGE_ROWS;
    int cg = tid & 31;
    int rg = tid >> 5;

    for (int t = blockIdx.x; t < ntiles; t += gridDim.x) {
        int r0 = t * SAGE_ROWS;
        if (tid < SAGE_ROWS) {
            int node = r0 + tid;
            float dg = (node < N_NODES) ? g_deg[node] : 1.f;
            idS[tid] = 1.f / fmaxf(dg, 1.f);
        }
        __syncthreads();
        for (int i = tid; i < SAGE_ROWS * 32; i += 512) {
            int row = i >> 5;
            int c4  = i & 31;
            int node = r0 + row;
            float4 m, xv;
            if (node < N_NODES) {
                m  = ((const float4*)(g_msg + (size_t)node * H))[c4];
                float inv = idS[row];
                m.x *= inv; m.y *= inv; m.z *= inv; m.w *= inv;
                xv = ((const float4*)(xin + (size_t)node * H))[c4];
            } else { m = make_float4(0.f,0.f,0.f,0.f); xv = m; }
            ((float4*)aS)[i] = m;
            ((float4*)xS)[i] = xv;
        }
        __syncthreads();

        float acc[4][4];
        #pragma unroll
        for (int i = 0; i < 4; i++)
            #pragma unroll
            for (int j = 0; j < 4; j++) acc[i][j] = 0.f;

        #pragma unroll 4
        for (int k = 0; k < D; k++) {
            float4 wl = *(const float4*)(WlS + k * 128 + cg * 4);
            float4 wr = *(const float4*)(WrS + k * 128 + cg * 4);
            #pragma unroll
            for (int i = 0; i < 4; i++) {
                float a  = aS[(rg * 4 + i) * 128 + k];
                float xx = xS[(rg * 4 + i) * 128 + k];
                acc[i][0] = fmaf(a, wl.x, acc[i][0]);
                acc[i][1] = fmaf(a, wl.y, acc[i][1]);
                acc[i][2] = fmaf(a, wl.z, acc[i][2]);
                acc[i][3] = fmaf(a, wl.w, acc[i][3]);
                acc[i][0] = fmaf(xx, wr.x, acc[i][0]);
                acc[i][1] = fmaf(xx, wr.y, acc[i][1]);
                acc[i][2] = fmaf(xx, wr.z, acc[i][2]);
                acc[i][3] = fmaf(xx, wr.w, acc[i][3]);
            }
        }
        float4 bb = *(const float4*)(b + cg * 4);
        #pragma unroll
        for (int i = 0; i < 4; i++) {
            int node = r0 + rg * 4 + i;
            if (node < N_NODES) {
                float4 o;
                o.x = fmaxf(acc[i][0] + bb.x, 0.f);
                o.y = fmaxf(acc[i][1] + bb.y, 0.f);
                o.z = fmaxf(acc[i][2] + bb.z, 0.f);
                o.w = fmaxf(acc[i][3] + bb.w, 0.f);
                *(float4*)(out + (size_t)node * H + cg * 4) = o;
            }
        }
        __syncthreads();
    }
}

// ================ tensor-pipe edge classifier (mma.sync tf32) ================
// Tile = 32 edges. feat [32 x 272] x W1 [272 x 128] -> relu -> x W2 [128 x 64]
// -> relu -> dot Wc3 -> sigmoid. W1/W2 resident in smem (padded strides for
// conflict-free fragment loads), feat/z1/z2 share one smem region.

__device__ __forceinline__ void mma_tf32(float* d, const uint32_t* a,
                                         const uint32_t* b) {
    asm volatile(
        "mma.sync.aligned.m16n8k8.row.col.f32.tf32.tf32.f32 "
        "{%0,%1,%2,%3}, {%4,%5,%6,%7}, {%8,%9}, {%0,%1,%2,%3};\n"
        : "+f"(d[0]), "+f"(d[1]), "+f"(d[2]), "+f"(d[3])
        : "r"(a[0]), "r"(a[1]), "r"(a[2]), "r"(a[3]),
          "r"(b[0]), "r"(b[1]));
}

#define ETILE 32
#define KF 272
#define FSTRIDE 276     // feat row stride (floats): conflict-free A frags
#define Z1STRIDE 132    // z1 row stride: conflict-free A frags
#define Z2STRIDE 66
#define W1STRIDE 136    // conflict-free B frags
#define W2STRIDE 72

#define OFF_FEATF 0
#define OFF_W1F   (ETILE * FSTRIDE)            // 8832
#define OFF_W2F   (OFF_W1F + KF * W1STRIDE)    // 8832 + 36992 = 45824
#define OFF_BIASF (OFF_W2F + 128 * W2STRIDE)   // 45824 + 9216 = 55040
#define CLS_SMEM_FLOATS (OFF_BIASF + 256)      // 55296 -> 221184 B
#define NTILES (N_EDGES / ETILE)               // 50000

__global__ void __launch_bounds__(512, 1) cls_mma_kernel(
    const float* __restrict__ h, const int* __restrict__ src,
    const int* __restrict__ dst, const float* __restrict__ eattr,
    const float* __restrict__ Wc1, const float* __restrict__ bc1,
    const float* __restrict__ Wc2, const float* __restrict__ bc2,
    const float* __restrict__ Wc3, const float* __restrict__ bc3,
    float* __restrict__ out)
{
    extern __shared__ float sm[];
    float* featS = sm + OFF_FEATF;   // also z1 (stride 132) and z2 (after z1)
    float* W1S   = sm + OFF_W1F;
    float* W2S   = sm + OFF_W2F;
    float* biasS = sm + OFF_BIASF;   // [0..127] bc1, [128..191] bc2, [192..255] Wc3
    float* z1S   = featS;
    float* z2S   = featS + ETILE * Z1STRIDE;   // 4224 floats in

    int tid  = threadIdx.x;
    int wid  = tid >> 5;
    int lane = tid & 31;
    int lr   = lane >> 2;   // 0..7
    int lc   = lane & 3;    // 0..3

    // resident weights (padded strides)
    for (int i = tid; i < KF * 32; i += 512) {          // 272 rows x 32 float4
        int r = i >> 5, c4 = i & 31;
        *(float4*)(W1S + r * W1STRIDE + c4 * 4) = *(const float4*)(Wc1 + r * 128 + c4 * 4);
    }
    for (int i = tid; i < 128 * 16; i += 512) {         // 128 rows x 16 float4
        int r = i >> 4, c4 = i & 15;
        *(float4*)(W2S + r * W2STRIDE + c4 * 4) = *(const float4*)(Wc2 + r * 64 + c4 * 4);
    }
    if (tid < 128)      biasS[tid] = bc1[tid];
    else if (tid < 192) biasS[tid] = bc2[tid - 128];
    else if (tid < 256) biasS[tid] = Wc3[tid - 192];
    float bc3v = __ldg(bc3);
    __syncthreads();

    // warp tiling: GEMM1 grid M2 x N8 (warp tile 16x16), GEMM2 M2 x N8 (16x8)
    int mt  = wid & 1;        // m-tile: rows mt*16
    int nt  = wid >> 1;       // 0..7

    // gather mapping: 16 threads per edge
    int ge = tid >> 4;        // edge slot 0..31
    int gq = tid & 15;

    for (int t = blockIdx.x; t < NTILES; t += gridDim.x) {
        int e0 = t * ETILE;
        __syncthreads();   // protect feat region reuse across iterations

        // ---- gather feat tile [32][272] (stride 276) ----
        {
            int s = __ldg(src + e0 + ge);
            int d = __ldg(dst + e0 + ge);
            const float4* hs = (const float4*)(h + (size_t)s * H);
            const float4* hd = (const float4*)(h + (size_t)d * H);
            float* frow = featS + ge * FSTRIDE;
            #pragma unroll
            for (int i = 0; i < 2; i++) {
                int c4 = gq * 2 + i;                 // 0..31
                *(float4*)(frow + c4 * 4)       = hs[c4];
                *(float4*)(frow + 128 + c4 * 4) = hd[c4];
            }
            if (gq < 4)
                *(float4*)(frow + 256 + gq * 4) =
                    ((const float4*)eattr)[(size_t)(e0 + ge) * 4 + gq];
        }
        __syncthreads();

        // ---- GEMM1: z1[32][128] = feat @ W1 ----
        float acc[2][4];
        #pragma unroll
        for (int f = 0; f < 2; f++)
            #pragma unroll
            for (int j = 0; j < 4; j++) acc[f][j] = 0.f;

        #pragma unroll 2
        for (int k0 = 0; k0 < KF; k0 += 8) {
            uint32_t a[4];
            const float* fp = featS + (mt * 16 + lr) * FSTRIDE + k0 + lc;
            a[0] = __float_as_uint(fp[0]);
            a[1] = __float_as_uint(fp[8 * FSTRIDE]);
            a[2] = __float_as_uint(fp[4]);
            a[3] = __float_as_uint(fp[8 * FSTRIDE + 4]);
            #pragma unroll
            for (int f = 0; f < 2; f++) {
                int n = nt * 16 + f * 8 + lr;
                uint32_t b[2];
                b[0] = __float_as_uint(W1S[(k0 + lc) * W1STRIDE + n]);
                b[1] = __float_as_uint(W1S[(k0 + 4 + lc) * W1STRIDE + n]);
                mma_tf32(acc[f], a, b);
            }
        }
        __syncthreads();   // all warps done reading featS before z1 overwrite

        // ---- epilogue 1: z1 = relu(acc + bc1) -> smem (stride 132) ----
        {
            int row0 = mt * 16 + lr;
            #pragma unroll
            for (int f = 0; f < 2; f++) {
                int col = nt * 16 + f * 8 + 2 * lc;
                float2 v0, v1;
                v0.x = fmaxf(acc[f][0] + biasS[col], 0.f);
                v0.y = fmaxf(acc[f][1] + biasS[col + 1], 0.f);
                v1.x = fmaxf(acc[f][2] + biasS[col], 0.f);
                v1.y = fmaxf(acc[f][3] + biasS[col + 1], 0.f);
                *(float2*)(z1S + row0 * Z1STRIDE + col) = v0;
                *(float2*)(z1S + (row0 + 8) * Z1STRIDE + col) = v1;
            }
        }
        __syncthreads();

        // ---- GEMM2: z2[32][64] = z1 @ W2 ----
        float acc2[4];
        #pragma unroll
        for (int j = 0; j < 4; j++) acc2[j] = 0.f;
        #pragma unroll 4
        for (int k0 = 0; k0 < 128; k0 += 8) {
            uint32_t a[4];
            const float* zp = z1S + (mt * 16 + lr) * Z1STRIDE + k0 + lc;
            a[0] = __float_as_uint(zp[0]);
            a[1] = __float_as_uint(zp[8 * Z1STRIDE]);
            a[2] = __float_as_uint(zp[4]);
            a[3] = __float_as_uint(zp[8 * Z1STRIDE + 4]);
            int n = nt * 8 + lr;
            uint32_t b[2];
            b[0] = __float_as_uint(W2S[(k0 + lc) * W2STRIDE + n]);
            b[1] = __float_as_uint(W2S[(k0 + 4 + lc) * W2STRIDE + n]);
            mma_tf32(acc2, a, b);
        }

        // ---- epilogue 2: z2 = relu(acc2 + bc2) -> smem (stride 66) ----
        {
            int row0 = mt * 16 + lr;
            int col = nt * 8 + 2 * lc;
            float2 v0, v1;
            v0.x = fmaxf(acc2[0] + biasS[128 + col], 0.f);
            v0.y = fmaxf(acc2[1] + biasS[128 + col + 1], 0.f);
            v1.x = fmaxf(acc2[2] + biasS[128 + col], 0.f);
            v1.y = fmaxf(acc2[3] + biasS[128 + col + 1], 0.f);
            *(float2*)(z2S + row0 * Z2STRIDE + col) = v0;
            *(float2*)(z2S + (row0 + 8) * Z2STRIDE + col) = v1;
        }
        __syncthreads();

        // ---- final: dot(z2[e], Wc3) + bc3 -> sigmoid ----
        {
            const float* zp = z2S + ge * Z2STRIDE + gq * 4;
            float2 p0 = *(const float2*)(zp);
            float2 p1 = *(const float2*)(zp + 2);
            const float* w = biasS + 192 + gq * 4;
            float acc3 = p0.x * w[0] + p0.y * w[1] + p1.x * w[2] + p1.y * w[3];
            acc3 += __shfl_xor_sync(0xffffffffu, acc3, 1);
            acc3 += __shfl_xor_sync(0xffffffffu, acc3, 2);
            acc3 += __shfl_xor_sync(0xffffffffu, acc3, 4);
            acc3 += __shfl_xor_sync(0xffffffffu, acc3, 8);
            if (gq == 0)
                out[e0 + ge] = 1.f / (1.f + expf(-(acc3 + bc3v)));
        }
    }
}

// ---------------- launch ----------------
extern "C" void kernel_launch(void* const* d_in, const int* in_sizes, int n_in,
                              void* d_out, int out_size) {
    const float* x     = (const float*)d_in[0];
    const int*   ei    = (const int*)d_in[1];
    const float* eattr = (const float*)d_in[2];
    const float* Wl0   = (const float*)d_in[3];
    const float* Wr0   = (const float*)d_in[4];
    const float* b0    = (const float*)d_in[5];
    const float* Wl1   = (const float*)d_in[6];
    const float* Wr1   = (const float*)d_in[7];
    const float* b1    = (const float*)d_in[8];
    const float* Wc1   = (const float*)d_in[9];
    const float* bc1   = (const float*)d_in[10];
    const float* Wc2   = (const float*)d_in[11];
    const float* bc2   = (const float*)d_in[12];
    const float* Wc3   = (const float*)d_in[13];
    const float* bc3   = (const float*)d_in[14];
    const int* src = ei;
    const int* dst = ei + N_EDGES;
    float* out = (float*)d_out;

    int sm_count = 148;
    cudaDeviceGetAttribute(&sm_count, cudaDevAttrMultiProcessorCount, 0);

    size_t sage_smem = SAGE_SMEM_FLOATS * sizeof(float);
    size_t cls_smem  = CLS_SMEM_FLOATS * sizeof(float);   // 221,184 B
    cudaFuncSetAttribute(sage_kernel, cudaFuncAttributeMaxDynamicSharedMemorySize,
                         (int)sage_smem);
    cudaFuncSetAttribute(cls_mma_kernel, cudaFuncAttributeMaxDynamicSharedMemorySize,
                         (int)cls_smem);

    int scatter_blocks = (N_EDGES * 32) / 256;

    // layer 0
    zero_kernel<<<4096, 256>>>(1);
    scatter_kernel<<<scatter_blocks, 256>>>(x, src, dst, 1);
    sage_kernel<<<sm_count, 512, sage_smem>>>(x, Wl0, Wr0, b0, g_h0);

    // layer 1 (deg unchanged, reuse)
    zero_kernel<<<4096, 256>>>(0);
    scatter_kernel<<<scatter_blocks, 256>>>(g_h0, src, dst, 0);
    sage_kernel<<<sm_count, 512, sage_smem>>>(g_h0, Wl1, Wr1, b1, g_h1);

    // tensor-pipe classifier
    cls_mma_kernel<<<sm_count, 512, cls_smem>>>(g_h1, src, dst, eattr,
                                                Wc1, bc1, Wc2, bc2, Wc3, bc3, out);
}